// round 9
// baseline (speedup 1.0000x reference)
#include <cuda_runtime.h>
#include <cuda_bf16.h>
#include <cstdint>

#define BWIN 4096
#define NTOK 49
#define DIMV 256
#define NH   8
#define HD   32
#define MTOT (BWIN*NTOK)              /* 200704 */
#define QSCALE 0.17677669529663687f   /* 32^-0.5 */

// ================= scratch (device globals; no allocation allowed) =========
__device__ __nv_bfloat16 g_xhi[(size_t)MTOT * DIMV];
__device__ __nv_bfloat16 g_xlo[(size_t)MTOT * DIMV];
__device__ __nv_bfloat16 g_chi[(size_t)MTOT * DIMV];
__device__ __nv_bfloat16 g_clo[(size_t)MTOT * DIMV];
__device__ __nv_bfloat16 g_wqh[768 * 256];
__device__ __nv_bfloat16 g_wql[768 * 256];
__device__ __nv_bfloat16 g_wph[256 * 256];
__device__ __nv_bfloat16 g_wpl[256 * 256];
__device__ float g_Q[(size_t)BWIN * NH * NTOK * HD];
__device__ float g_K[(size_t)BWIN * NH * NTOK * HD];
__device__ float g_V[(size_t)BWIN * NH * NTOK * HD];

// ======================= helpers ===========================================
__device__ __forceinline__ uint32_t smem_u32(const void* p) {
    uint32_t a;
    asm("{ .reg .u64 t; cvta.to.shared.u64 t, %1; cvt.u32.u64 %0, t; }" : "=r"(a) : "l"(p));
    return a;
}
__device__ __forceinline__ void cp16(uint32_t sdst, const void* g) {
    asm volatile("cp.async.cg.shared.global [%0], [%1], 16;" :: "r"(sdst), "l"(g));
}
#define CP_COMMIT() asm volatile("cp.async.commit_group;" ::: "memory")

__device__ __forceinline__ void ldsm_x4(uint32_t (&r)[4], uint32_t addr) {
    asm volatile("ldmatrix.sync.aligned.m8n8.x4.shared.b16 {%0,%1,%2,%3}, [%4];"
                 : "=r"(r[0]), "=r"(r[1]), "=r"(r[2]), "=r"(r[3]) : "r"(addr));
}
__device__ __forceinline__ void mma16816(float (&d)[4], const uint32_t (&a)[4],
                                         uint32_t b0, uint32_t b1) {
    asm volatile("mma.sync.aligned.m16n8k16.row.col.f32.bf16.bf16.f32 "
                 "{%0,%1,%2,%3}, {%4,%5,%6,%7}, {%8,%9}, {%0,%1,%2,%3};"
                 : "+f"(d[0]), "+f"(d[1]), "+f"(d[2]), "+f"(d[3])
                 : "r"(a[0]), "r"(a[1]), "r"(a[2]), "r"(a[3]), "r"(b0), "r"(b1));
}

// ======================= split / pack kernels ==============================
__global__ __launch_bounds__(256) void k_split_x(const float* __restrict__ in,
                                                 __nv_bfloat16* __restrict__ hi,
                                                 __nv_bfloat16* __restrict__ lo) {
    size_t gi = ((size_t)blockIdx.x * 256 + threadIdx.x) * 4;
    float4 v = *(const float4*)(in + gi);
    __nv_bfloat16 h0 = __float2bfloat16(v.x), h1 = __float2bfloat16(v.y);
    __nv_bfloat16 h2 = __float2bfloat16(v.z), h3 = __float2bfloat16(v.w);
    __nv_bfloat162 hA = __halves2bfloat162(h0, h1), hB = __halves2bfloat162(h2, h3);
    __nv_bfloat162 lA = __halves2bfloat162(__float2bfloat16(v.x - __bfloat162float(h0)),
                                           __float2bfloat16(v.y - __bfloat162float(h1)));
    __nv_bfloat162 lB = __halves2bfloat162(__float2bfloat16(v.z - __bfloat162float(h2)),
                                           __float2bfloat16(v.w - __bfloat162float(h3)));
    *(__nv_bfloat162*)(hi + gi)     = hA; *(__nv_bfloat162*)(hi + gi + 2) = hB;
    *(__nv_bfloat162*)(lo + gi)     = lA; *(__nv_bfloat162*)(lo + gi + 2) = lB;
}

__global__ __launch_bounds__(256) void k_split_w(const float* __restrict__ w,
                                                 __nv_bfloat16* __restrict__ hi,
                                                 __nv_bfloat16* __restrict__ lo, int N) {
    int i = blockIdx.x * 256 + threadIdx.x;   // over 256*N
    int k = i / N, n = i - k * N;
    float v = w[i];
    __nv_bfloat16 h = __float2bfloat16(v);
    hi[(size_t)n * 256 + k] = h;
    lo[(size_t)n * 256 + k] = __float2bfloat16(v - __bfloat162float(h));
}

// ======================= HMMA GEMM =========================================
// C tile 128 x (NWN*32) = (Ahi+Alo)*(Bhi+Blo)^T, 3-term compensated.
// NWN*2 warps (warp tile 64x32), BK=32, NSTG-stage cp.async, 1 barrier/iter.
template<int EPI, int NWN, int NSTG, int WAITN>
__global__ __launch_bounds__(NWN * 64, 1) void mma_gemm(const float* __restrict__ bias,
                                                        float* __restrict__ out) {
    extern __shared__ char smem[];
    const uint32_t sb = smem_u32(smem);
    constexpr int BN = NWN * 32;
    constexpr int T = NWN * 64;
    constexpr int PITCH = 80;                       // 32 bf16 (64B) + 16B pad
    constexpr uint32_t ATILE = 128 * PITCH;         // 10240 B
    constexpr uint32_t BTILE = BN * PITCH;
    constexpr uint32_t STAGE = 2 * ATILE + 2 * BTILE;
    constexpr int ITERS = 8;                        // 256 / 32

    const int tid = threadIdx.x;
    const int wid = tid >> 5, lane = tid & 31;
    const int warp_m = wid & 1, warp_n = wid >> 1;  // warp_n in [0, NWN)

    const __nv_bfloat16* gAh = (EPI ? g_chi : g_xhi) + (size_t)blockIdx.y * 128 * 256;
    const __nv_bfloat16* gAl = (EPI ? g_clo : g_xlo) + (size_t)blockIdx.y * 128 * 256;
    const __nv_bfloat16* gBh = (EPI ? g_wph : g_wqh) + (size_t)blockIdx.x * BN * 256;
    const __nv_bfloat16* gBl = (EPI ? g_wpl : g_wql) + (size_t)blockIdx.x * BN * 256;

    float acc[4][4][4];
#pragma unroll
    for (int a = 0; a < 4; a++)
#pragma unroll
        for (int b = 0; b < 4; b++)
#pragma unroll
            for (int c = 0; c < 4; c++) acc[a][b][c] = 0.f;

    auto load_stage = [&](int it, int s) {
        const int k0 = it * 32;
        const uint32_t st = sb + (uint32_t)s * STAGE;
#pragma unroll
        for (int slot = tid; slot < 512; slot += T) {     // A: 128 rows x 4 chunks
            int r = slot >> 2, c = slot & 3;
            size_t goff = (size_t)r * 256 + k0 + c * 8;
            uint32_t soff = (uint32_t)(r * PITCH + c * 16);
            cp16(st + soff,         gAh + goff);
            cp16(st + ATILE + soff, gAl + goff);
        }
#pragma unroll
        for (int slot = tid; slot < BN * 4; slot += T) {  // B: BN rows x 4 chunks
            int r = slot >> 2, c = slot & 3;
            size_t goff = (size_t)r * 256 + k0 + c * 8;
            uint32_t soff = (uint32_t)(r * PITCH + c * 16);
            cp16(st + 2 * ATILE + soff,         gBh + goff);
            cp16(st + 2 * ATILE + BTILE + soff, gBl + goff);
        }
        CP_COMMIT();
    };

    // ldmatrix lane address components
    const int a_row = (lane & 7) + 8 * ((lane >> 3) & 1);
    const int a_kb  = ((lane >> 4) & 1) * 16;
    const int b_row = (lane & 7) + 8 * ((lane >> 4) & 1);
    const int b_kb  = ((lane >> 3) & 1) * 16;

#pragma unroll
    for (int p = 0; p < NSTG - 1; p++) load_stage(p, p);

#pragma unroll 1
    for (int it = 0; it < ITERS; ++it) {
        if (it < ITERS - (NSTG - 1))
            asm volatile("cp.async.wait_group %0;" :: "n"(WAITN) : "memory");
        else
            asm volatile("cp.async.wait_group 0;" ::: "memory");
        __syncthreads();

        if (it + NSTG - 1 < ITERS) load_stage(it + NSTG - 1, (it + NSTG - 1) % NSTG);

        const int s = it % NSTG;
        const uint32_t sAh = sb + (uint32_t)s * STAGE;
        const uint32_t sAl = sAh + ATILE;
        const uint32_t sBh = sAl + ATILE;
        const uint32_t sBl = sBh + BTILE;
#pragma unroll
        for (int h16 = 0; h16 < 2; h16++) {
            const int kb = h16 * 32;
            uint32_t bhi[2][4], blo[2][4];
#pragma unroll
            for (int np = 0; np < 2; np++) {
                uint32_t boff = (uint32_t)((warp_n * 32 + np * 16 + b_row) * PITCH + kb + b_kb);
                ldsm_x4(bhi[np], sBh + boff);
                ldsm_x4(blo[np], sBl + boff);
            }
            uint32_t ahi[4][4], alo[4][4];
#pragma unroll
            for (int mi = 0; mi < 4; mi++) {
                uint32_t aoff = (uint32_t)((warp_m * 64 + mi * 16 + a_row) * PITCH + kb + a_kb);
                ldsm_x4(ahi[mi], sAh + aoff);
                ldsm_x4(alo[mi], sAl + aoff);
            }
#pragma unroll
            for (int mi = 0; mi < 4; mi++) {
                mma16816(acc[mi][0], ahi[mi], bhi[0][0], bhi[0][1]);
                mma16816(acc[mi][1], ahi[mi], bhi[0][2], bhi[0][3]);
                mma16816(acc[mi][2], ahi[mi], bhi[1][0], bhi[1][1]);
                mma16816(acc[mi][3], ahi[mi], bhi[1][2], bhi[1][3]);
            }
#pragma unroll
            for (int mi = 0; mi < 4; mi++) {
                mma16816(acc[mi][0], ahi[mi], blo[0][0], blo[0][1]);
                mma16816(acc[mi][1], ahi[mi], blo[0][2], blo[0][3]);
                mma16816(acc[mi][2], ahi[mi], blo[1][0], blo[1][1]);
                mma16816(acc[mi][3], ahi[mi], blo[1][2], blo[1][3]);
            }
#pragma unroll
            for (int mi = 0; mi < 4; mi++) {
                mma16816(acc[mi][0], alo[mi], bhi[0][0], bhi[0][1]);
                mma16816(acc[mi][1], alo[mi], bhi[0][2], bhi[0][3]);
                mma16816(acc[mi][2], alo[mi], bhi[1][0], bhi[1][1]);
                mma16816(acc[mi][3], alo[mi], bhi[1][2], bhi[1][3]);
            }
        }
    }

    // ---------------- epilogue ----------------
    const int row0 = blockIdx.y * 128 + warp_m * 64;
    const int col0 = blockIdx.x * BN + warp_n * 32;

    if (EPI == 1) {
#pragma unroll
        for (int mi = 0; mi < 4; mi++) {
#pragma unroll
            for (int ni = 0; ni < 4; ni++) {
                int col = col0 + ni * 8 + (lane & 3) * 2;
                float bx0 = bias[col], bx1 = bias[col + 1];
                int r0 = row0 + mi * 16 + (lane >> 2);
                float2 v0 = make_float2(acc[mi][ni][0] + bx0, acc[mi][ni][1] + bx1);
                float2 v1 = make_float2(acc[mi][ni][2] + bx0, acc[mi][ni][3] + bx1);
                *(float2*)(out + (size_t)r0 * 256 + col)       = v0;
                *(float2*)(out + (size_t)(r0 + 8) * 256 + col) = v1;
            }
        }
    } else {
#pragma unroll
        for (int mi = 0; mi < 4; mi++) {
#pragma unroll
            for (int ni = 0; ni < 4; ni++) {
#pragma unroll
                for (int id = 0; id < 4; id++) {
                    int row = row0 + mi * 16 + (lane >> 2) + 8 * (id >> 1);
                    int col = col0 + ni * 8 + (lane & 3) * 2 + (id & 1);
                    float v = acc[mi][ni][id] + bias[col];
                    int s2 = col % 3;
                    int hd = col / 3;
                    int h = hd >> 5, d = hd & 31;
                    int b = row / 49, n = row - b * 49;
                    size_t addr = (size_t)(b * NH + h) * (NTOK * HD) + n * HD + d;
                    if (s2 == 0)      g_Q[addr] = v * QSCALE;
                    else if (s2 == 1) g_K[addr] = v;
                    else              g_V[addr] = v;
                }
            }
        }
    }
}

// ======================= attention (unchanged from R6) =====================
#define KPITCH 36
#define PPITCH 52
__global__ __launch_bounds__(256)
void attn_kernel(const int* __restrict__ mask, const float* __restrict__ bias_table)
{
    __shared__ float sQ[NTOK * HD];
    __shared__ float sK[NTOK * KPITCH];
    __shared__ float sV[NTOK * HD];
    __shared__ float sP[NTOK * PPITCH];
    __shared__ float sBias[169];

    const int bh = blockIdx.x;
    const int b = bh >> 3, h = bh & 7;
    const int tid = threadIdx.x;
    const int warp = tid >> 5, lane = tid & 31;

    const float4* Qb = (const float4*)(g_Q + (size_t)bh * NTOK * HD);
    const float4* Kb = (const float4*)(g_K + (size_t)bh * NTOK * HD);
    const float4* Vb = (const float4*)(g_V + (size_t)bh * NTOK * HD);

    for (int i = tid; i < NTOK * 8; i += 256) {
        ((float4*)sQ)[i] = Qb[i];
        ((float4*)sV)[i] = Vb[i];
        float4 kv = Kb[i];
        int r = i >> 3, c = (i & 7) << 2;
        *(float4*)(sK + r * KPITCH + c) = kv;
    }
    if (tid < 169) sBias[tid] = bias_table[tid * NH + h];
    __syncthreads();

    const int k0 = lane, k1 = lane + 32;
    const bool v1 = (k1 < NTOK);
    const int ki0 = k0 / 7, kj0 = k0 - ki0 * 7;
    const int ki1 = k1 / 7, kj1 = k1 - ki1 * 7;
    const float* kr0 = sK + k0 * KPITCH;
    const float* kr1 = sK + (v1 ? k1 : k0) * KPITCH;

    for (int q = warp; q < NTOK; q += 8) {
        float s0 = 0.f, s1 = 0.f;
        const float* qrow = sQ + q * HD;
#pragma unroll
        for (int d4 = 0; d4 < 8; d4++) {
            float4 qv = *(const float4*)(qrow + d4 * 4);
            float4 a0 = *(const float4*)(kr0 + d4 * 4);
            float4 a1 = *(const float4*)(kr1 + d4 * 4);
            s0 = fmaf(qv.x, a0.x, s0); s1 = fmaf(qv.x, a1.x, s1);
            s0 = fmaf(qv.y, a0.y, s0); s1 = fmaf(qv.y, a1.y, s1);
            s0 = fmaf(qv.z, a0.z, s0); s1 = fmaf(qv.z, a1.z, s1);
            s0 = fmaf(qv.w, a0.w, s0); s1 = fmaf(qv.w, a1.w, s1);
        }
        const int qi = q / 7, qj = q - qi * 7;
        const int* mrow = mask + (size_t)b * (NTOK * NTOK) + q * NTOK;
        int m0 = mrow[k0];
        int m1 = v1 ? mrow[k1] : 0;
        s0 += sBias[(qi - ki0 + 6) * 13 + (qj - kj0 + 6)] + (1.0f - (float)m0) * (-1e10f);
        if (v1) s1 += sBias[(qi - ki1 + 6) * 13 + (qj - kj1 + 6)] + (1.0f - (float)m1) * (-1e10f);
        else    s1 = -3.0e38f;

        float mx = fmaxf(s0, s1);
#pragma unroll
        for (int off = 16; off; off >>= 1)
            mx = fmaxf(mx, __shfl_xor_sync(0xffffffffu, mx, off));
        float e0 = __expf(s0 - mx);
        float e1 = v1 ? __expf(s1 - mx) : 0.f;
        float sum = e0 + e1;
#pragma unroll
        for (int off = 16; off; off >>= 1)
            sum += __shfl_xor_sync(0xffffffffu, sum, off);
        float inv = 1.0f / sum;
        sP[q * PPITCH + k0] = e0 * inv;
        if (v1) sP[q * PPITCH + k1] = e1 * inv;
    }
    __syncthreads();

    __nv_bfloat16* chiw = g_chi + ((size_t)b * NTOK) * DIMV + h * HD;
    __nv_bfloat16* clow = g_clo + ((size_t)b * NTOK) * DIMV + h * HD;
#pragma unroll 1
    for (int e = tid; e < NTOK * HD; e += 256) {
        int qq = e >> 5, d = e & 31;
        const float* pr = sP + qq * PPITCH;
        float s0 = 0.f, s1 = 0.f;
#pragma unroll
        for (int k = 0; k < 48; k += 2) {
            s0 = fmaf(pr[k],     sV[k * HD + d],       s0);
            s1 = fmaf(pr[k + 1], sV[(k + 1) * HD + d], s1);
        }
        float s = s0 + s1 + pr[48] * sV[48 * HD + d];
        __nv_bfloat16 hv = __float2bfloat16(s);
        chiw[(size_t)qq * DIMV + d] = hv;
        clow[(size_t)qq * DIMV + d] = __float2bfloat16(s - __bfloat162float(hv));
    }
}

// ============================================================================
extern "C" void kernel_launch(void* const* d_in, const int* in_sizes, int n_in,
                              void* d_out, int out_size)
{
    const float* x       = (const float*)d_in[0];
    const int*   mask    = (const int*)d_in[1];
    const float* qkv_w   = (const float*)d_in[2];
    const float* qkv_b   = (const float*)d_in[3];
    const float* proj_w  = (const float*)d_in[4];
    const float* proj_b  = (const float*)d_in[5];
    const float* rel_tbl = (const float*)d_in[6];
    float* out = (float*)d_out;

    __nv_bfloat16 *xhi, *xlo, *wqh, *wql, *wph, *wpl;
    cudaGetSymbolAddress((void**)&xhi, g_xhi);
    cudaGetSymbolAddress((void**)&xlo, g_xlo);
    cudaGetSymbolAddress((void**)&wqh, g_wqh);
    cudaGetSymbolAddress((void**)&wql, g_wql);
    cudaGetSymbolAddress((void**)&wph, g_wph);
    cudaGetSymbolAddress((void**)&wpl, g_wpl);

    // QKV: BN=192 (NWN=6), 384 thr, 3 stages, wait 1 : smem 3*51200 = 153600
    constexpr int SMEM_Q = 3 * (2 * 128 * 80 + 2 * 192 * 80);
    // proj: BN=128 (NWN=4), 256 thr, 2 stages, wait 0 : smem 2*40960 = 81920
    constexpr int SMEM_P = 2 * (2 * 128 * 80 + 2 * 128 * 80);
    cudaFuncSetAttribute((void*)mma_gemm<0, 6, 3, 1>, cudaFuncAttributeMaxDynamicSharedMemorySize, SMEM_Q);
    cudaFuncSetAttribute((void*)mma_gemm<1, 4, 2, 0>, cudaFuncAttributeMaxDynamicSharedMemorySize, SMEM_P);

    k_split_x<<<MTOT * 256 / 1024, 256>>>(x, xhi, xlo);
    k_split_w<<<768, 256>>>(qkv_w, wqh, wql, 768);
    k_split_w<<<256, 256>>>(proj_w, wph, wpl, 256);

    // QKV GEMM: 4 col tiles of 192, 1568 row tiles
    mma_gemm<0, 6, 3, 1><<<dim3(4, MTOT / 128), 384, SMEM_Q>>>(qkv_b, nullptr);

    attn_kernel<<<BWIN * NH, 256>>>(mask, rel_tbl);

    // proj GEMM: 2 col tiles of 128
    mma_gemm<1, 4, 2, 0><<<dim3(2, MTOT / 128), 256, SMEM_P>>>(proj_b, out);
}

// round 10
// speedup vs baseline: 1.1643x; 1.1643x over previous
#include <cuda_runtime.h>
#include <cuda_bf16.h>
#include <cstdint>

#define BWIN 4096
#define NTOK 49
#define DIMV 256
#define NH   8
#define HD   32
#define MTOT (BWIN*NTOK)              /* 200704 */
#define QSCALE 0.17677669529663687f   /* 32^-0.5 */

// ================= scratch (device globals; no allocation allowed) =========
__device__ __nv_bfloat16 g_xhi[(size_t)MTOT * DIMV];
__device__ __nv_bfloat16 g_xlo[(size_t)MTOT * DIMV];
__device__ __nv_bfloat16 g_chi[(size_t)MTOT * DIMV];
__device__ __nv_bfloat16 g_clo[(size_t)MTOT * DIMV];
__device__ __nv_bfloat16 g_wqh[768 * 256];
__device__ __nv_bfloat16 g_wql[768 * 256];
__device__ __nv_bfloat16 g_wph[256 * 256];
__device__ __nv_bfloat16 g_wpl[256 * 256];
__device__ float g_Q[(size_t)BWIN * NH * NTOK * HD];
__device__ float g_K[(size_t)BWIN * NH * NTOK * HD];
__device__ float g_V[(size_t)BWIN * NH * NTOK * HD];

// ======================= helpers ===========================================
__device__ __forceinline__ uint32_t smem_u32(const void* p) {
    uint32_t a;
    asm("{ .reg .u64 t; cvta.to.shared.u64 t, %1; cvt.u32.u64 %0, t; }" : "=r"(a) : "l"(p));
    return a;
}
__device__ __forceinline__ void cp16(uint32_t sdst, const void* g) {
    asm volatile("cp.async.cg.shared.global [%0], [%1], 16;" :: "r"(sdst), "l"(g));
}
#define CP_COMMIT() asm volatile("cp.async.commit_group;" ::: "memory")

__device__ __forceinline__ void ldsm_x4(uint32_t (&r)[4], uint32_t addr) {
    asm volatile("ldmatrix.sync.aligned.m8n8.x4.shared.b16 {%0,%1,%2,%3}, [%4];"
                 : "=r"(r[0]), "=r"(r[1]), "=r"(r[2]), "=r"(r[3]) : "r"(addr));
}
__device__ __forceinline__ void mma16816(float (&d)[4], const uint32_t (&a)[4],
                                         uint32_t b0, uint32_t b1) {
    asm volatile("mma.sync.aligned.m16n8k16.row.col.f32.bf16.bf16.f32 "
                 "{%0,%1,%2,%3}, {%4,%5,%6,%7}, {%8,%9}, {%0,%1,%2,%3};"
                 : "+f"(d[0]), "+f"(d[1]), "+f"(d[2]), "+f"(d[3])
                 : "r"(a[0]), "r"(a[1]), "r"(a[2]), "r"(a[3]), "r"(b0), "r"(b1));
}

// ======================= split / pack kernels ==============================
__global__ __launch_bounds__(256) void k_split_x(const float* __restrict__ in,
                                                 __nv_bfloat16* __restrict__ hi,
                                                 __nv_bfloat16* __restrict__ lo) {
    size_t gi = ((size_t)blockIdx.x * 256 + threadIdx.x) * 4;
    float4 v = *(const float4*)(in + gi);
    __nv_bfloat16 h0 = __float2bfloat16(v.x), h1 = __float2bfloat16(v.y);
    __nv_bfloat16 h2 = __float2bfloat16(v.z), h3 = __float2bfloat16(v.w);
    __nv_bfloat162 hA = __halves2bfloat162(h0, h1), hB = __halves2bfloat162(h2, h3);
    __nv_bfloat162 lA = __halves2bfloat162(__float2bfloat16(v.x - __bfloat162float(h0)),
                                           __float2bfloat16(v.y - __bfloat162float(h1)));
    __nv_bfloat162 lB = __halves2bfloat162(__float2bfloat16(v.z - __bfloat162float(h2)),
                                           __float2bfloat16(v.w - __bfloat162float(h3)));
    *(__nv_bfloat162*)(hi + gi)     = hA; *(__nv_bfloat162*)(hi + gi + 2) = hB;
    *(__nv_bfloat162*)(lo + gi)     = lA; *(__nv_bfloat162*)(lo + gi + 2) = lB;
}

__global__ __launch_bounds__(256) void k_split_w(const float* __restrict__ w,
                                                 __nv_bfloat16* __restrict__ hi,
                                                 __nv_bfloat16* __restrict__ lo, int N) {
    int i = blockIdx.x * 256 + threadIdx.x;   // over 256*N
    int k = i / N, n = i - k * N;
    float v = w[i];
    __nv_bfloat16 h = __float2bfloat16(v);
    hi[(size_t)n * 256 + k] = h;
    lo[(size_t)n * 256 + k] = __float2bfloat16(v - __bfloat162float(h));
}

// ======================= HMMA GEMM (exact R6 config) =======================
// C tile 128x128 = (Ahi+Alo)[M,256]*(Bhi+Blo)[N,256]^T, 3-term compensated.
// BK=32, 2-stage cp.async double buffer, 256 threads, 2 CTAs/SM.
template<int EPI>
__global__ __launch_bounds__(256, 2) void mma_gemm(const float* __restrict__ bias,
                                                   float* __restrict__ out) {
    extern __shared__ char smem[];
    const uint32_t sb = smem_u32(smem);
    constexpr int PITCH = 80;
    constexpr uint32_t TILE = 128 * PITCH;
    constexpr uint32_t STAGE = 4 * TILE;
    constexpr int ITERS = 8;

    const int tid = threadIdx.x;
    const int wid = tid >> 5, lane = tid & 31;
    const int warp_m = wid & 1, warp_n = wid >> 1;

    const __nv_bfloat16* gAh = (EPI ? g_chi : g_xhi) + (size_t)blockIdx.y * 128 * 256;
    const __nv_bfloat16* gAl = (EPI ? g_clo : g_xlo) + (size_t)blockIdx.y * 128 * 256;
    const __nv_bfloat16* gBh = (EPI ? g_wph : g_wqh) + (size_t)blockIdx.x * 128 * 256;
    const __nv_bfloat16* gBl = (EPI ? g_wpl : g_wql) + (size_t)blockIdx.x * 128 * 256;

    float acc[4][4][4];
#pragma unroll
    for (int a = 0; a < 4; a++)
#pragma unroll
        for (int b = 0; b < 4; b++)
#pragma unroll
            for (int c = 0; c < 4; c++) acc[a][b][c] = 0.f;

    const int lr = tid >> 2;
    const int lc = tid & 3;
    auto load_stage = [&](int it, int s) {
        const int k0 = it * 32;
        const uint32_t st = sb + (uint32_t)s * STAGE;
#pragma unroll
        for (int j = 0; j < 8; j++) {
            const __nv_bfloat16* base = (j < 2) ? gAh : (j < 4) ? gAl : (j < 6) ? gBh : gBl;
            int r = lr + (j & 1) * 64;
            cp16(st + (uint32_t)(j >> 1) * TILE + (uint32_t)(r * PITCH + lc * 16),
                 base + (size_t)r * 256 + k0 + lc * 8);
        }
        CP_COMMIT();
    };

    const int a_row = (lane & 7) + 8 * ((lane >> 3) & 1);
    const int a_kb  = ((lane >> 4) & 1) * 16;
    const int b_row = (lane & 7) + 8 * ((lane >> 4) & 1);
    const int b_kb  = ((lane >> 3) & 1) * 16;

    load_stage(0, 0);

    int s = 0;
#pragma unroll 1
    for (int it = 0; it < ITERS; ++it) {
        asm volatile("cp.async.wait_group 0;" ::: "memory");
        __syncthreads();
        if (it + 1 < ITERS) load_stage(it + 1, s ^ 1);

        const uint32_t sAh = sb + (uint32_t)s * STAGE;
        const uint32_t sAl = sAh + TILE;
        const uint32_t sBh = sAl + TILE;
        const uint32_t sBl = sBh + TILE;
#pragma unroll
        for (int h16 = 0; h16 < 2; h16++) {
            const int kb = h16 * 32;
            uint32_t bhi[2][4], blo[2][4];
#pragma unroll
            for (int np = 0; np < 2; np++) {
                uint32_t boff = (uint32_t)((warp_n * 32 + np * 16 + b_row) * PITCH + kb + b_kb);
                ldsm_x4(bhi[np], sBh + boff);
                ldsm_x4(blo[np], sBl + boff);
            }
            uint32_t ahi[4][4], alo[4][4];
#pragma unroll
            for (int mi = 0; mi < 4; mi++) {
                uint32_t aoff = (uint32_t)((warp_m * 64 + mi * 16 + a_row) * PITCH + kb + a_kb);
                ldsm_x4(ahi[mi], sAh + aoff);
                ldsm_x4(alo[mi], sAl + aoff);
            }
#pragma unroll
            for (int mi = 0; mi < 4; mi++) {
                mma16816(acc[mi][0], ahi[mi], bhi[0][0], bhi[0][1]);
                mma16816(acc[mi][1], ahi[mi], bhi[0][2], bhi[0][3]);
                mma16816(acc[mi][2], ahi[mi], bhi[1][0], bhi[1][1]);
                mma16816(acc[mi][3], ahi[mi], bhi[1][2], bhi[1][3]);
            }
#pragma unroll
            for (int mi = 0; mi < 4; mi++) {
                mma16816(acc[mi][0], ahi[mi], blo[0][0], blo[0][1]);
                mma16816(acc[mi][1], ahi[mi], blo[0][2], blo[0][3]);
                mma16816(acc[mi][2], ahi[mi], blo[1][0], blo[1][1]);
                mma16816(acc[mi][3], ahi[mi], blo[1][2], blo[1][3]);
            }
#pragma unroll
            for (int mi = 0; mi < 4; mi++) {
                mma16816(acc[mi][0], alo[mi], bhi[0][0], bhi[0][1]);
                mma16816(acc[mi][1], alo[mi], bhi[0][2], bhi[0][3]);
                mma16816(acc[mi][2], alo[mi], bhi[1][0], bhi[1][1]);
                mma16816(acc[mi][3], alo[mi], bhi[1][2], bhi[1][3]);
            }
        }
        s ^= 1;
    }

    const int row0 = blockIdx.y * 128 + warp_m * 64;
    const int col0 = blockIdx.x * 128 + warp_n * 32;

    if (EPI == 1) {
#pragma unroll
        for (int mi = 0; mi < 4; mi++) {
#pragma unroll
            for (int ni = 0; ni < 4; ni++) {
                int col = col0 + ni * 8 + (lane & 3) * 2;
                float bx0 = bias[col], bx1 = bias[col + 1];
                int r0 = row0 + mi * 16 + (lane >> 2);
                float2 v0 = make_float2(acc[mi][ni][0] + bx0, acc[mi][ni][1] + bx1);
                float2 v1 = make_float2(acc[mi][ni][2] + bx0, acc[mi][ni][3] + bx1);
                *(float2*)(out + (size_t)r0 * 256 + col)       = v0;
                *(float2*)(out + (size_t)(r0 + 8) * 256 + col) = v1;
            }
        }
    } else {
#pragma unroll
        for (int mi = 0; mi < 4; mi++) {
#pragma unroll
            for (int ni = 0; ni < 4; ni++) {
#pragma unroll
                for (int id = 0; id < 4; id++) {
                    int row = row0 + mi * 16 + (lane >> 2) + 8 * (id >> 1);
                    int col = col0 + ni * 8 + (lane & 3) * 2 + (id & 1);
                    float v = acc[mi][ni][id] + bias[col];
                    int s2 = col % 3;
                    int hd = col / 3;
                    int h = hd >> 5, d = hd & 31;
                    int b = row / 49, n = row - b * 49;
                    size_t addr = (size_t)(b * NH + h) * (NTOK * HD) + n * HD + d;
                    if (s2 == 0)      g_Q[addr] = v * QSCALE;
                    else if (s2 == 1) g_K[addr] = v;
                    else              g_V[addr] = v;
                }
            }
        }
    }
}

// ======================= attention v3: smem-staged mask =====================
#define KPITCH 36
#define PPITCH 52
__global__ __launch_bounds__(256)
void attn_kernel(const int* __restrict__ mask, const float* __restrict__ bias_table)
{
    __shared__ float sQ[NTOK * HD];
    __shared__ float sK[NTOK * KPITCH];
    __shared__ float sV[NTOK * HD];
    __shared__ float sP[NTOK * PPITCH];
    __shared__ float sBias[169];
    __shared__ float sMask[NTOK * NTOK];     // additive penalty

    const int bh = blockIdx.x;
    const int b = bh >> 3, h = bh & 7;
    const int tid = threadIdx.x;
    const int warp = tid >> 5, lane = tid & 31;

    const float4* Qb = (const float4*)(g_Q + (size_t)bh * NTOK * HD);
    const float4* Kb = (const float4*)(g_K + (size_t)bh * NTOK * HD);
    const float4* Vb = (const float4*)(g_V + (size_t)bh * NTOK * HD);
    const int* mbase = mask + (size_t)b * (NTOK * NTOK);

    for (int i = tid; i < NTOK * 8; i += 256) {
        ((float4*)sQ)[i] = Qb[i];
        ((float4*)sV)[i] = Vb[i];
        float4 kv = Kb[i];
        int r = i >> 3, c = (i & 7) << 2;
        *(float4*)(sK + r * KPITCH + c) = kv;
    }
#pragma unroll
    for (int i = tid; i < NTOK * NTOK; i += 256)
        sMask[i] = (1.0f - (float)mbase[i]) * (-1e10f);
    if (tid < 169) sBias[tid] = bias_table[tid * NH + h];
    __syncthreads();

    const int k0 = lane, k1 = lane + 32;
    const bool v1 = (k1 < NTOK);
    const int ki0 = k0 / 7, kj0 = k0 - ki0 * 7;
    const int ki1 = k1 / 7, kj1 = k1 - ki1 * 7;
    const float* kr0 = sK + k0 * KPITCH;
    const float* kr1 = sK + (v1 ? k1 : k0) * KPITCH;

    for (int q = warp; q < NTOK; q += 8) {
        float s0 = 0.f, s1 = 0.f;
        const float* qrow = sQ + q * HD;
#pragma unroll
        for (int d4 = 0; d4 < 8; d4++) {
            float4 qv = *(const float4*)(qrow + d4 * 4);
            float4 a0 = *(const float4*)(kr0 + d4 * 4);
            float4 a1 = *(const float4*)(kr1 + d4 * 4);
            s0 = fmaf(qv.x, a0.x, s0); s1 = fmaf(qv.x, a1.x, s1);
            s0 = fmaf(qv.y, a0.y, s0); s1 = fmaf(qv.y, a1.y, s1);
            s0 = fmaf(qv.z, a0.z, s0); s1 = fmaf(qv.z, a1.z, s1);
            s0 = fmaf(qv.w, a0.w, s0); s1 = fmaf(qv.w, a1.w, s1);
        }
        const int qi = q / 7, qj = q - qi * 7;
        s0 += sBias[(qi - ki0 + 6) * 13 + (qj - kj0 + 6)] + sMask[q * NTOK + k0];
        if (v1) s1 += sBias[(qi - ki1 + 6) * 13 + (qj - kj1 + 6)] + sMask[q * NTOK + k1];
        else    s1 = -3.0e38f;

        float mx = fmaxf(s0, s1);
#pragma unroll
        for (int off = 16; off; off >>= 1)
            mx = fmaxf(mx, __shfl_xor_sync(0xffffffffu, mx, off));
        float e0 = __expf(s0 - mx);
        float e1 = v1 ? __expf(s1 - mx) : 0.f;
        float sum = e0 + e1;
#pragma unroll
        for (int off = 16; off; off >>= 1)
            sum += __shfl_xor_sync(0xffffffffu, sum, off);
        float inv = 1.0f / sum;
        sP[q * PPITCH + k0] = e0 * inv;
        if (v1) sP[q * PPITCH + k1] = e1 * inv;
    }
    __syncthreads();

    __nv_bfloat16* chiw = g_chi + ((size_t)b * NTOK) * DIMV + h * HD;
    __nv_bfloat16* clow = g_clo + ((size_t)b * NTOK) * DIMV + h * HD;
#pragma unroll 1
    for (int e = tid; e < NTOK * HD; e += 256) {
        int qq = e >> 5, d = e & 31;
        const float* pr = sP + qq * PPITCH;
        float s0 = 0.f, s1 = 0.f;
#pragma unroll
        for (int k = 0; k < 48; k += 2) {
            s0 = fmaf(pr[k],     sV[k * HD + d],       s0);
            s1 = fmaf(pr[k + 1], sV[(k + 1) * HD + d], s1);
        }
        float s = s0 + s1 + pr[48] * sV[48 * HD + d];
        __nv_bfloat16 hv = __float2bfloat16(s);
        chiw[(size_t)qq * DIMV + d] = hv;
        clow[(size_t)qq * DIMV + d] = __float2bfloat16(s - __bfloat162float(hv));
    }
}

// ============================================================================
extern "C" void kernel_launch(void* const* d_in, const int* in_sizes, int n_in,
                              void* d_out, int out_size)
{
    const float* x       = (const float*)d_in[0];
    const int*   mask    = (const int*)d_in[1];
    const float* qkv_w   = (const float*)d_in[2];
    const float* qkv_b   = (const float*)d_in[3];
    const float* proj_w  = (const float*)d_in[4];
    const float* proj_b  = (const float*)d_in[5];
    const float* rel_tbl = (const float*)d_in[6];
    float* out = (float*)d_out;

    __nv_bfloat16 *xhi, *xlo, *wqh, *wql, *wph, *wpl;
    cudaGetSymbolAddress((void**)&xhi, g_xhi);
    cudaGetSymbolAddress((void**)&xlo, g_xlo);
    cudaGetSymbolAddress((void**)&wqh, g_wqh);
    cudaGetSymbolAddress((void**)&wql, g_wql);
    cudaGetSymbolAddress((void**)&wph, g_wph);
    cudaGetSymbolAddress((void**)&wpl, g_wpl);

    constexpr int SMEMB = 2 * 4 * 128 * 80;    // 81920
    cudaFuncSetAttribute(mma_gemm<0>, cudaFuncAttributeMaxDynamicSharedMemorySize, SMEMB);
    cudaFuncSetAttribute(mma_gemm<1>, cudaFuncAttributeMaxDynamicSharedMemorySize, SMEMB);

    k_split_x<<<MTOT * 256 / 1024, 256>>>(x, xhi, xlo);
    k_split_w<<<768, 256>>>(qkv_w, wqh, wql, 768);
    k_split_w<<<256, 256>>>(proj_w, wph, wpl, 256);

    mma_gemm<0><<<dim3(6, MTOT / 128), 256, SMEMB>>>(qkv_b, nullptr);

    attn_kernel<<<BWIN * NH, 256>>>(mask, rel_tbl);

    mma_gemm<1><<<dim3(2, MTOT / 128), 256, SMEMB>>>(proj_b, out);
}